// round 9
// baseline (speedup 1.0000x reference)
#include <cuda_runtime.h>
#include <cuda_bf16.h>
#include <cstdint>

#define N_NODES 50000
#define E_EDGES 625000
#define HIDDEN  128

// ---------------- scratch ----------------------------------------------------
__device__ float g_sum[N_NODES * HIDDEN];
__device__ int   g_count[N_NODES];
__device__ int   g_offset[N_NODES];
__device__ int   g_cursor[N_NODES];
__device__ int   g_edge_ids[E_EDGES];
__device__ int   g_bar;

// ---------------- 1. histogram ------------------------------------------------
__global__ void hist4_kernel(const int4* __restrict__ er4) {
    int t = blockIdx.x * blockDim.x + threadIdx.x;
    if (t < E_EDGES / 4) {
        int4 r = er4[t];
        atomicAdd(&g_count[r.x], 1);
        atomicAdd(&g_count[r.y], 1);
        atomicAdd(&g_count[r.z], 1);
        atomicAdd(&g_count[r.w], 1);
    }
}

// ---------------- 2. exclusive scan -------------------------------------------
__global__ void scan_kernel() {
    __shared__ int s[1024];
    const int t = threadIdx.x;
    const int CHUNK = (N_NODES + 1023) / 1024;
    int base = t * CHUNK;
    int sum = 0;
    for (int i = 0; i < CHUNK; i++) {
        int idx = base + i;
        if (idx < N_NODES) sum += g_count[idx];
    }
    s[t] = sum;
    __syncthreads();
    for (int off = 1; off < 1024; off <<= 1) {
        int v = 0;
        if (t >= off) v = s[t - off];
        __syncthreads();
        if (t >= off) s[t] += v;
        __syncthreads();
    }
    int run = (t == 0) ? 0 : s[t - 1];
    for (int i = 0; i < CHUNK; i++) {
        int idx = base + i;
        if (idx < N_NODES) {
            g_offset[idx] = run;
            g_cursor[idx] = run;
            run += g_count[idx];
        }
    }
}

// ---------------- 3. fused CSR-fill + gather ---------------------------------
#define FG_CTAS 592

__global__ __launch_bounds__(256, 4)
void fillgather_kernel(const int4* __restrict__ er4,
                       const float* __restrict__ edge_attr) {
    const int nthr = gridDim.x * blockDim.x;

    for (int t = blockIdx.x * blockDim.x + threadIdx.x; t < E_EDGES / 4; t += nthr) {
        int4 r = er4[t];
        int base = t * 4;
        int p0 = atomicAdd(&g_cursor[r.x], 1); g_edge_ids[p0] = base + 0;
        int p1 = atomicAdd(&g_cursor[r.y], 1); g_edge_ids[p1] = base + 1;
        int p2 = atomicAdd(&g_cursor[r.z], 1); g_edge_ids[p2] = base + 2;
        int p3 = atomicAdd(&g_cursor[r.w], 1); g_edge_ids[p3] = base + 3;
    }

    __threadfence();
    __syncthreads();
    if (threadIdx.x == 0) {
        atomicAdd(&g_bar, 1);
        while (*(volatile int*)&g_bar < (int)gridDim.x) { __nanosleep(64); }
    }
    __syncthreads();
    __threadfence();

    const int lane   = threadIdx.x & 31;
    const int gw     = (blockIdx.x * blockDim.x + threadIdx.x) >> 5;
    const int nwarps = nthr >> 5;
    const float4* ea4 = (const float4*)edge_attr;

    for (int node = gw; node < N_NODES; node += nwarps) {
        int start = g_offset[node];
        int cnt   = g_count[node];
        float4 acc = make_float4(0.f, 0.f, 0.f, 0.f);
        int i = 0;
        for (; i + 8 <= cnt; i += 8) {
            int e[8];
            #pragma unroll
            for (int u = 0; u < 8; u++) e[u] = g_edge_ids[start + i + u];
            float4 v[8];
            #pragma unroll
            for (int u = 0; u < 8; u++) v[u] = ea4[(size_t)e[u] * 32 + lane];
            #pragma unroll
            for (int u = 0; u < 8; u++) {
                acc.x += v[u].x; acc.y += v[u].y; acc.z += v[u].z; acc.w += v[u].w;
            }
        }
        for (; i < cnt; i++) {
            int e = g_edge_ids[start + i];
            float4 v = ea4[(size_t)e * 32 + lane];
            acc.x += v.x; acc.y += v.y; acc.z += v.z; acc.w += v.w;
        }
        ((float4*)g_sum)[(size_t)node * 32 + lane] = acc;
    }
}

// ---------------- 4. MLP: 512 threads, register-lean nf-halved ---------------
__device__ __forceinline__ void mma_bf16(float4& d,
    uint32_t a0, uint32_t a1, uint32_t a2, uint32_t a3,
    uint32_t b0, uint32_t b1) {
    asm volatile(
        "mma.sync.aligned.m16n8k16.row.col.f32.bf16.bf16.f32 "
        "{%0,%1,%2,%3}, {%4,%5,%6,%7}, {%8,%9}, {%0,%1,%2,%3};"
        : "+f"(d.x), "+f"(d.y), "+f"(d.z), "+f"(d.w)
        : "r"(a0), "r"(a1), "r"(a2), "r"(a3), "r"(b0), "r"(b1));
}
__device__ __forceinline__ void split2(float a, float b, uint32_t& hi, uint32_t& lo) {
    __nv_bfloat16 ha = __float2bfloat16_rn(a);
    __nv_bfloat16 hb = __float2bfloat16_rn(b);
    __nv_bfloat162 H; H.x = ha; H.y = hb;
    hi = *(uint32_t*)&H;
    __nv_bfloat162 L;
    L.x = __float2bfloat16_rn(a - __bfloat162float(ha));
    L.y = __float2bfloat16_rn(b - __bfloat162float(hb));
    lo = *(uint32_t*)&L;
}

#define TILE_M  256
#define N_TILES ((N_NODES + TILE_M - 1) / TILE_M)   // 196
#define W1_BYTES (128 * 68 * 16)   // 139264
#define W2_BYTES (128 * 36 * 16)   // 73728
#define MLP_SMEM (W1_BYTES + W2_BYTES + 256 * 4)    // 214016

__global__ __launch_bounds__(512, 1)
void mlp_mma_kernel(const float* __restrict__ x,
                    const float* __restrict__ W1, const float* __restrict__ b1,
                    const float* __restrict__ W2, const float* __restrict__ b2,
                    float* __restrict__ out) {
    extern __shared__ char smem[];
    char*  W1i = smem;
    char*  W2i = smem + W1_BYTES;
    float* b1s = (float*)(smem + W1_BYTES + W2_BYTES);
    float* b2s = b1s + 128;

    const int tid = threadIdx.x;

    // ---- stage W1/W2 interleaved + split ----
    for (int i = tid; i < 256 * 128; i += 512) {
        int k = i >> 7, j = i & 127;
        float v = W1[i];
        __nv_bfloat16 h = __float2bfloat16_rn(v);
        __nv_bfloat16 l = __float2bfloat16_rn(v - __bfloat162float(h));
        int ks = k >> 4, m = k & 15;
        int q = (m & 7) >> 1, s = m & 1, t = m >> 3;
        char* p8 = W1i + ((j * 68 + ks * 4 + q) << 4) + t * 4 + s * 2;
        *(__nv_bfloat16*)p8 = h;
        *(__nv_bfloat16*)(p8 + 8) = l;
    }
    for (int i = tid; i < 128 * 128; i += 512) {
        int k = i >> 7, j = i & 127;
        float v = W2[i];
        __nv_bfloat16 h = __float2bfloat16_rn(v);
        __nv_bfloat16 l = __float2bfloat16_rn(v - __bfloat162float(h));
        int ks = k >> 4, m = k & 15;
        int q = (m & 7) >> 1, s = m & 1, t = m >> 3;
        char* p8 = W2i + ((j * 36 + ks * 4 + q) << 4) + t * 4 + s * 2;
        *(__nv_bfloat16*)p8 = h;
        *(__nv_bfloat16*)(p8 + 8) = l;
    }
    if (tid < 128) { b1s[tid] = b1[tid]; b2s[tid] = b2[tid]; }
    __syncthreads();
    // no syncs below: warps independent

    const int w    = tid >> 5;      // 0..15
    const int lane = tid & 31;
    const int p    = lane >> 2;
    const int q    = lane & 3;
    const char* B1p = W1i + ((p * 68 + q) << 4);
    const char* B2p = W2i + ((p * 36 + q) << 4);

    for (int tile = blockIdx.x; tile < N_TILES; tile += gridDim.x) {
        const int row0 = tile * TILE_M + w * 16 + p;
        const int row1 = row0 + 8;
        const bool ok0 = row0 < N_NODES;
        const bool ok1 = row1 < N_NODES;
        const float* xr0 = x + (size_t)row0 * 128;
        const float* xr1 = x + (size_t)row1 * 128;
        const float* sr0 = g_sum + (size_t)row0 * 128;
        const float* sr1 = g_sum + (size_t)row1 * 128;
        const float2 z = make_float2(0.f, 0.f);

        // persistent hidden fragments for this warp's 16 nodes
        uint32_t ah[8][4], al[8][4];

        // ---- layer 1 in two nf-halves (acc = 8 frags = 32 regs) ----
        #pragma unroll
        for (int h = 0; h < 2; h++) {
            float4 acc[8];
            #pragma unroll
            for (int nf = 0; nf < 8; nf++) acc[nf] = make_float4(0.f, 0.f, 0.f, 0.f);

            #pragma unroll
            for (int ks = 0; ks < 16; ks++) {
                const float* p0 = (ks < 8) ? xr0 : sr0;
                const float* p1 = (ks < 8) ? xr1 : sr1;
                const int ko = (ks & 7) * 16 + q * 2;
                float2 v00 = ok0 ? *(const float2*)(p0 + ko)     : z;
                float2 v01 = ok0 ? *(const float2*)(p0 + ko + 8) : z;
                float2 v10 = ok1 ? *(const float2*)(p1 + ko)     : z;
                float2 v11 = ok1 ? *(const float2*)(p1 + ko + 8) : z;
                uint32_t a0h, a0l, a1h, a1l, a2h, a2l, a3h, a3l;
                split2(v00.x, v00.y, a0h, a0l);
                split2(v10.x, v10.y, a1h, a1l);
                split2(v01.x, v01.y, a2h, a2l);
                split2(v11.x, v11.y, a3h, a3l);
                const char* wp = B1p + ks * 64 + h * 8 * 8704;
                #pragma unroll
                for (int nf = 0; nf < 8; nf++) {
                    uint4 bw = *(const uint4*)(wp + nf * 8704);   // 8*68*16
                    mma_bf16(acc[nf], a0h, a1h, a2h, a3h, bw.x, bw.y);
                    mma_bf16(acc[nf], a0h, a1h, a2h, a3h, bw.z, bw.w);
                    mma_bf16(acc[nf], a0l, a1l, a2l, a3l, bw.x, bw.y);
                }
            }
            // bias + relu + split -> ah/al[h*4 .. h*4+3]
            #pragma unroll
            for (int nf = 0; nf < 8; nf++) {
                const int gnf = h * 8 + nf;
                const int ks2 = gnf >> 1;          // h*4 + nf/2
                const int half = gnf & 1;
                float2 bv = *(const float2*)&b1s[gnf * 8 + q * 2];
                float hx = fmaxf(acc[nf].x + bv.x, 0.f);
                float hy = fmaxf(acc[nf].y + bv.y, 0.f);
                float hz = fmaxf(acc[nf].z + bv.x, 0.f);
                float hw = fmaxf(acc[nf].w + bv.y, 0.f);
                split2(hx, hy, ah[ks2][half * 2 + 0], al[ks2][half * 2 + 0]);
                split2(hz, hw, ah[ks2][half * 2 + 1], al[ks2][half * 2 + 1]);
            }
        }

        // ---- layer 2 in two nf-halves (acc2 = 8 frags = 32 regs) ----
        #pragma unroll
        for (int h2 = 0; h2 < 2; h2++) {
            float4 acc2[8];
            #pragma unroll
            for (int nf = 0; nf < 8; nf++) acc2[nf] = make_float4(0.f, 0.f, 0.f, 0.f);

            #pragma unroll
            for (int ks2 = 0; ks2 < 8; ks2++) {
                const char* wp = B2p + ks2 * 64 + h2 * 8 * 4608;
                #pragma unroll
                for (int nf = 0; nf < 8; nf++) {
                    uint4 bw = *(const uint4*)(wp + nf * 4608);   // 8*36*16
                    mma_bf16(acc2[nf], ah[ks2][0], ah[ks2][1], ah[ks2][2], ah[ks2][3], bw.x, bw.y);
                    mma_bf16(acc2[nf], ah[ks2][0], ah[ks2][1], ah[ks2][2], ah[ks2][3], bw.z, bw.w);
                    mma_bf16(acc2[nf], al[ks2][0], al[ks2][1], al[ks2][2], al[ks2][3], bw.x, bw.y);
                }
            }
            // epilogue: + b2 + residual, store
            #pragma unroll
            for (int nf = 0; nf < 8; nf++) {
                const int j = (h2 * 8 + nf) * 8 + q * 2;
                float2 bv = *(const float2*)&b2s[j];
                if (ok0) {
                    float2 xr = *(const float2*)(xr0 + j);
                    float2 o = make_float2(acc2[nf].x + bv.x + xr.x,
                                           acc2[nf].y + bv.y + xr.y);
                    *(float2*)(out + (size_t)row0 * 128 + j) = o;
                }
                if (ok1) {
                    float2 xr = *(const float2*)(xr1 + j);
                    float2 o = make_float2(acc2[nf].z + bv.x + xr.x,
                                           acc2[nf].w + bv.y + xr.y);
                    *(float2*)(out + (size_t)row1 * 128 + j) = o;
                }
            }
        }
    }
}

// ---------------- launcher ---------------------------------------------------
extern "C" void kernel_launch(void* const* d_in, const int* in_sizes, int n_in,
                              void* d_out, int out_size) {
    const float* x          = (const float*)d_in[0];
    const int*   edge_row   = (const int*)d_in[1];   // int64 downcast; first E = row
    const float* edge_attr  = (const float*)d_in[2];
    const float* W1         = (const float*)d_in[5];
    const float* b1         = (const float*)d_in[6];
    const float* W2         = (const float*)d_in[7];
    const float* b2         = (const float*)d_in[8];
    float*       out        = (float*)d_out;

    void* gcnt = nullptr;
    cudaGetSymbolAddress(&gcnt, g_count);
    cudaMemsetAsync(gcnt, 0, N_NODES * sizeof(int));
    void* gbar = nullptr;
    cudaGetSymbolAddress(&gbar, g_bar);
    cudaMemsetAsync(gbar, 0, sizeof(int));

    hist4_kernel<<<(E_EDGES / 4 + 255) / 256, 256>>>((const int4*)edge_row);   // 1
    scan_kernel<<<1, 1024>>>();                                                // 2
    fillgather_kernel<<<FG_CTAS, 256>>>((const int4*)edge_row, edge_attr);     // 3
    cudaFuncSetAttribute(mlp_mma_kernel, cudaFuncAttributeMaxDynamicSharedMemorySize, MLP_SMEM);
    mlp_mma_kernel<<<148, 512, MLP_SMEM>>>(x, W1, b1, W2, b2, out);            // 4 (profiled)
}

// round 10
// speedup vs baseline: 1.4437x; 1.4437x over previous
#include <cuda_runtime.h>
#include <cuda_bf16.h>
#include <cstdint>

#define N_NODES 50000
#define E_EDGES 625000
#define HIDDEN  128

// ---------------- scratch ----------------------------------------------------
__device__ float g_sum[N_NODES * HIDDEN];
__device__ int   g_count[N_NODES];
__device__ int   g_offset[N_NODES];
__device__ int   g_cursor[N_NODES];
__device__ int   g_edge_ids[E_EDGES];
__device__ int   g_part[592];
__device__ int   g_bar;

// ---------------- fused prologue: hist + scan + fill + gather ----------------
#define FG_CTAS 592
#define CHUNK_N 85   // 592 * 85 = 50320 >= N_NODES

__device__ __forceinline__ void grid_barrier(int target) {
    __threadfence();
    __syncthreads();
    if (threadIdx.x == 0) {
        atomicAdd(&g_bar, 1);
        while (*(volatile int*)&g_bar < target) { __nanosleep(32); }
    }
    __syncthreads();
    __threadfence();
}

__global__ __launch_bounds__(256, 4)
void prologue_kernel(const int4* __restrict__ er4,
                     const float* __restrict__ edge_attr) {
    const int nthr = gridDim.x * blockDim.x;
    const int gtid = blockIdx.x * blockDim.x + threadIdx.x;
    __shared__ int scnt[CHUNK_N];
    __shared__ int soff[CHUNK_N];
    __shared__ int sred[256];

    // ---- phase 1: histogram (g_count zeroed by host memset) ----
    for (int t = gtid; t < E_EDGES / 4; t += nthr) {
        int4 r = er4[t];
        atomicAdd(&g_count[r.x], 1);
        atomicAdd(&g_count[r.y], 1);
        atomicAdd(&g_count[r.z], 1);
        atomicAdd(&g_count[r.w], 1);
    }
    grid_barrier(1 * FG_CTAS);

    // ---- phase 2: local scan of this CTA's chunk ----
    const int base = blockIdx.x * CHUNK_N;
    for (int t = threadIdx.x; t < CHUNK_N; t += 256) {
        int idx = base + t;
        scnt[t] = (idx < N_NODES) ? g_count[idx] : 0;
    }
    __syncthreads();
    if (threadIdx.x == 0) {
        int run = 0;
        #pragma unroll 5
        for (int i = 0; i < CHUNK_N; i++) { soff[i] = run; run += scnt[i]; }
        g_part[blockIdx.x] = run;
    }
    grid_barrier(2 * FG_CTAS);

    // ---- phase 3: prefix of partials (redundant block-reduce) + finalize ----
    {
        int s = 0;
        for (int i = threadIdx.x; i < blockIdx.x; i += 256) s += g_part[i];
        sred[threadIdx.x] = s;
        __syncthreads();
        #pragma unroll
        for (int off = 128; off > 0; off >>= 1) {
            if (threadIdx.x < off) sred[threadIdx.x] += sred[threadIdx.x + off];
            __syncthreads();
        }
        int prefix = sred[0];
        for (int t = threadIdx.x; t < CHUNK_N; t += 256) {
            int idx = base + t;
            if (idx < N_NODES) {
                int o = soff[t] + prefix;
                g_offset[idx] = o;
                g_cursor[idx] = o;
            }
        }
    }
    grid_barrier(3 * FG_CTAS);

    // ---- phase 4: CSR fill ----
    for (int t = gtid; t < E_EDGES / 4; t += nthr) {
        int4 r = er4[t];
        int b4 = t * 4;
        int p0 = atomicAdd(&g_cursor[r.x], 1); g_edge_ids[p0] = b4 + 0;
        int p1 = atomicAdd(&g_cursor[r.y], 1); g_edge_ids[p1] = b4 + 1;
        int p2 = atomicAdd(&g_cursor[r.z], 1); g_edge_ids[p2] = b4 + 2;
        int p3 = atomicAdd(&g_cursor[r.w], 1); g_edge_ids[p3] = b4 + 3;
    }
    grid_barrier(4 * FG_CTAS);

    // ---- phase 5: gather segment-sum (warp per node) ----
    const int lane   = threadIdx.x & 31;
    const int gw     = gtid >> 5;
    const int nwarps = nthr >> 5;
    const float4* ea4 = (const float4*)edge_attr;

    for (int node = gw; node < N_NODES; node += nwarps) {
        int start = g_offset[node];
        int cnt   = g_count[node];
        float4 acc = make_float4(0.f, 0.f, 0.f, 0.f);
        int i = 0;
        for (; i + 8 <= cnt; i += 8) {
            int e[8];
            #pragma unroll
            for (int u = 0; u < 8; u++) e[u] = g_edge_ids[start + i + u];
            float4 v[8];
            #pragma unroll
            for (int u = 0; u < 8; u++) v[u] = ea4[(size_t)e[u] * 32 + lane];
            #pragma unroll
            for (int u = 0; u < 8; u++) {
                acc.x += v[u].x; acc.y += v[u].y; acc.z += v[u].z; acc.w += v[u].w;
            }
        }
        for (; i < cnt; i++) {
            int e = g_edge_ids[start + i];
            float4 v = ea4[(size_t)e * 32 + lane];
            acc.x += v.x; acc.y += v.y; acc.z += v.z; acc.w += v.w;
        }
        ((float4*)g_sum)[(size_t)node * 32 + lane] = acc;
    }
}

// ---------------- MLP via mma.sync (R8 config: 256 thr, TILE_M=128) ----------
__device__ __forceinline__ void mma_bf16(float4& d,
    uint32_t a0, uint32_t a1, uint32_t a2, uint32_t a3,
    uint32_t b0, uint32_t b1) {
    asm volatile(
        "mma.sync.aligned.m16n8k16.row.col.f32.bf16.bf16.f32 "
        "{%0,%1,%2,%3}, {%4,%5,%6,%7}, {%8,%9}, {%0,%1,%2,%3};"
        : "+f"(d.x), "+f"(d.y), "+f"(d.z), "+f"(d.w)
        : "r"(a0), "r"(a1), "r"(a2), "r"(a3), "r"(b0), "r"(b1));
}
__device__ __forceinline__ void split2(float a, float b, uint32_t& hi, uint32_t& lo) {
    __nv_bfloat16 ha = __float2bfloat16_rn(a);
    __nv_bfloat16 hb = __float2bfloat16_rn(b);
    __nv_bfloat162 H; H.x = ha; H.y = hb;
    hi = *(uint32_t*)&H;
    __nv_bfloat162 L;
    L.x = __float2bfloat16_rn(a - __bfloat162float(ha));
    L.y = __float2bfloat16_rn(b - __bfloat162float(hb));
    lo = *(uint32_t*)&L;
}

#define TILE_M  128
#define N_TILES ((N_NODES + TILE_M - 1) / TILE_M)   // 391
#define W1_BYTES (128 * 68 * 16)   // 139264
#define W2_BYTES (128 * 36 * 16)   // 73728
#define MLP_SMEM (W1_BYTES + W2_BYTES + 256 * 4)    // 214016

__global__ __launch_bounds__(256, 1)
void mlp_mma_kernel(const float* __restrict__ x,
                    const float* __restrict__ W1, const float* __restrict__ b1,
                    const float* __restrict__ W2, const float* __restrict__ b2,
                    float* __restrict__ out) {
    extern __shared__ char smem[];
    char*  W1i = smem;
    char*  W2i = smem + W1_BYTES;
    float* b1s = (float*)(smem + W1_BYTES + W2_BYTES);
    float* b2s = b1s + 128;

    const int tid = threadIdx.x;

    for (int i = tid; i < 256 * 128; i += 256) {
        int k = i >> 7, j = i & 127;
        float v = W1[i];
        __nv_bfloat16 h = __float2bfloat16_rn(v);
        __nv_bfloat16 l = __float2bfloat16_rn(v - __bfloat162float(h));
        int ks = k >> 4, m = k & 15;
        int q = (m & 7) >> 1, s = m & 1, t = m >> 3;
        char* p8 = W1i + ((j * 68 + ks * 4 + q) << 4) + t * 4 + s * 2;
        *(__nv_bfloat16*)p8 = h;
        *(__nv_bfloat16*)(p8 + 8) = l;
    }
    for (int i = tid; i < 128 * 128; i += 256) {
        int k = i >> 7, j = i & 127;
        float v = W2[i];
        __nv_bfloat16 h = __float2bfloat16_rn(v);
        __nv_bfloat16 l = __float2bfloat16_rn(v - __bfloat162float(h));
        int ks = k >> 4, m = k & 15;
        int q = (m & 7) >> 1, s = m & 1, t = m >> 3;
        char* p8 = W2i + ((j * 36 + ks * 4 + q) << 4) + t * 4 + s * 2;
        *(__nv_bfloat16*)p8 = h;
        *(__nv_bfloat16*)(p8 + 8) = l;
    }
    if (tid < 128) { b1s[tid] = b1[tid]; b2s[tid] = b2[tid]; }
    __syncthreads();

    const int w    = tid >> 5;
    const int lane = tid & 31;
    const int p    = lane >> 2;
    const int q    = lane & 3;
    const char* B1p = W1i + ((p * 68 + q) << 4);
    const char* B2p = W2i + ((p * 36 + q) << 4);

    for (int tile = blockIdx.x; tile < N_TILES; tile += gridDim.x) {
        const int row0 = tile * TILE_M + w * 16 + p;
        const int row1 = row0 + 8;
        const bool ok0 = row0 < N_NODES;
        const bool ok1 = row1 < N_NODES;
        const float* xr0 = x + (size_t)row0 * 128;
        const float* xr1 = x + (size_t)row1 * 128;
        const float* sr0 = g_sum + (size_t)row0 * 128;
        const float* sr1 = g_sum + (size_t)row1 * 128;

        float4 acc[16];
        #pragma unroll
        for (int nf = 0; nf < 16; nf++) acc[nf] = make_float4(0.f, 0.f, 0.f, 0.f);

        #pragma unroll
        for (int ks = 0; ks < 16; ks++) {
            const float* p0 = (ks < 8) ? xr0 : sr0;
            const float* p1 = (ks < 8) ? xr1 : sr1;
            const int ko = (ks & 7) * 16 + q * 2;
            float2 z = make_float2(0.f, 0.f);
            float2 v00 = ok0 ? *(const float2*)(p0 + ko)     : z;
            float2 v01 = ok0 ? *(const float2*)(p0 + ko + 8) : z;
            float2 v10 = ok1 ? *(const float2*)(p1 + ko)     : z;
            float2 v11 = ok1 ? *(const float2*)(p1 + ko + 8) : z;
            uint32_t a0h, a0l, a1h, a1l, a2h, a2l, a3h, a3l;
            split2(v00.x, v00.y, a0h, a0l);
            split2(v10.x, v10.y, a1h, a1l);
            split2(v01.x, v01.y, a2h, a2l);
            split2(v11.x, v11.y, a3h, a3l);
            const char* wp = B1p + ks * 64;
            #pragma unroll
            for (int nf = 0; nf < 16; nf++) {
                uint4 bw = *(const uint4*)(wp + nf * 8704);   // 8*68*16
                mma_bf16(acc[nf], a0h, a1h, a2h, a3h, bw.x, bw.y);
                mma_bf16(acc[nf], a0h, a1h, a2h, a3h, bw.z, bw.w);
                mma_bf16(acc[nf], a0l, a1l, a2l, a3l, bw.x, bw.y);
            }
        }

        uint32_t ah[8][4], al[8][4];
        #pragma unroll
        for (int ks2 = 0; ks2 < 8; ks2++) {
            #pragma unroll
            for (int half = 0; half < 2; half++) {
                const int nf = ks2 * 2 + half;
                float2 bv = *(const float2*)&b1s[nf * 8 + q * 2];
                float hx = fmaxf(acc[nf].x + bv.x, 0.f);
                float hy = fmaxf(acc[nf].y + bv.y, 0.f);
                float hz = fmaxf(acc[nf].z + bv.x, 0.f);
                float hw = fmaxf(acc[nf].w + bv.y, 0.f);
                split2(hx, hy, ah[ks2][half * 2 + 0], al[ks2][half * 2 + 0]);
                split2(hz, hw, ah[ks2][half * 2 + 1], al[ks2][half * 2 + 1]);
            }
        }

        float4 acc2[16];
        #pragma unroll
        for (int nf = 0; nf < 16; nf++) acc2[nf] = make_float4(0.f, 0.f, 0.f, 0.f);

        #pragma unroll
        for (int ks2 = 0; ks2 < 8; ks2++) {
            const char* wp = B2p + ks2 * 64;
            #pragma unroll
            for (int nf = 0; nf < 16; nf++) {
                uint4 bw = *(const uint4*)(wp + nf * 4608);   // 8*36*16
                mma_bf16(acc2[nf], ah[ks2][0], ah[ks2][1], ah[ks2][2], ah[ks2][3], bw.x, bw.y);
                mma_bf16(acc2[nf], ah[ks2][0], ah[ks2][1], ah[ks2][2], ah[ks2][3], bw.z, bw.w);
                mma_bf16(acc2[nf], al[ks2][0], al[ks2][1], al[ks2][2], al[ks2][3], bw.x, bw.y);
            }
        }

        #pragma unroll
        for (int nf = 0; nf < 16; nf++) {
            const int j = nf * 8 + q * 2;
            float2 bv = *(const float2*)&b2s[j];
            if (ok0) {
                float2 xr = *(const float2*)(xr0 + j);
                float2 o = make_float2(acc2[nf].x + bv.x + xr.x,
                                       acc2[nf].y + bv.y + xr.y);
                *(float2*)(out + (size_t)row0 * 128 + j) = o;
            }
            if (ok1) {
                float2 xr = *(const float2*)(xr1 + j);
                float2 o = make_float2(acc2[nf].z + bv.x + xr.x,
                                       acc2[nf].w + bv.y + xr.y);
                *(float2*)(out + (size_t)row1 * 128 + j) = o;
            }
        }
    }
}

// ---------------- launcher ---------------------------------------------------
extern "C" void kernel_launch(void* const* d_in, const int* in_sizes, int n_in,
                              void* d_out, int out_size) {
    const float* x          = (const float*)d_in[0];
    const int*   edge_row   = (const int*)d_in[1];   // int64 downcast; first E = row
    const float* edge_attr  = (const float*)d_in[2];
    const float* W1         = (const float*)d_in[5];
    const float* b1         = (const float*)d_in[6];
    const float* W2         = (const float*)d_in[7];
    const float* b2         = (const float*)d_in[8];
    float*       out        = (float*)d_out;

    void* gcnt = nullptr;
    cudaGetSymbolAddress(&gcnt, g_count);
    cudaMemsetAsync(gcnt, 0, N_NODES * sizeof(int));
    void* gbar = nullptr;
    cudaGetSymbolAddress(&gbar, g_bar);
    cudaMemsetAsync(gbar, 0, sizeof(int));

    prologue_kernel<<<FG_CTAS, 256>>>((const int4*)edge_row, edge_attr);   // kernel 1
    cudaFuncSetAttribute(mlp_mma_kernel, cudaFuncAttributeMaxDynamicSharedMemorySize, MLP_SMEM);
    mlp_mma_kernel<<<148, 256, MLP_SMEM>>>(x, W1, b1, W2, b2, out);        // kernel 2
}

// round 11
// speedup vs baseline: 1.5283x; 1.0586x over previous
#include <cuda_runtime.h>
#include <cuda_bf16.h>
#include <cstdint>

#define N_NODES 50000
#define E_EDGES 625000
#define HIDDEN  128

// ---------------- scratch ----------------------------------------------------
__device__ float g_sum[N_NODES * HIDDEN];
__device__ int   g_count[N_NODES];
__device__ int   g_offset[N_NODES];
__device__ int   g_cursor[N_NODES];
__device__ int   g_edge_ids[E_EDGES];
__device__ int   g_part[592];
__device__ int   g_bar;

// ---------------- fused prologue: hist + scan + fill + gather ----------------
#define FG_CTAS 592
#define CHUNK_N 85   // 592 * 85 = 50320 >= N_NODES

__device__ __forceinline__ void grid_barrier(int target) {
    __threadfence();
    __syncthreads();
    if (threadIdx.x == 0) {
        atomicAdd(&g_bar, 1);
        while (*(volatile int*)&g_bar < target) { __nanosleep(32); }
    }
    __syncthreads();
    __threadfence();
}

__global__ __launch_bounds__(256, 4)
void prologue_kernel(const int4* __restrict__ er4,
                     const float* __restrict__ edge_attr) {
    const int nthr = gridDim.x * blockDim.x;
    const int gtid = blockIdx.x * blockDim.x + threadIdx.x;
    __shared__ int scnt[CHUNK_N];
    __shared__ int soff[CHUNK_N];
    __shared__ int sred[256];

    // ---- phase 1: histogram (g_count zeroed by host memset) ----
    for (int t = gtid; t < E_EDGES / 4; t += nthr) {
        int4 r = er4[t];
        atomicAdd(&g_count[r.x], 1);
        atomicAdd(&g_count[r.y], 1);
        atomicAdd(&g_count[r.z], 1);
        atomicAdd(&g_count[r.w], 1);
    }
    grid_barrier(1 * FG_CTAS);

    // ---- phase 2: local scan of this CTA's chunk ----
    const int base = blockIdx.x * CHUNK_N;
    for (int t = threadIdx.x; t < CHUNK_N; t += 256) {
        int idx = base + t;
        scnt[t] = (idx < N_NODES) ? g_count[idx] : 0;
    }
    __syncthreads();
    if (threadIdx.x == 0) {
        int run = 0;
        #pragma unroll 5
        for (int i = 0; i < CHUNK_N; i++) { soff[i] = run; run += scnt[i]; }
        g_part[blockIdx.x] = run;
    }
    grid_barrier(2 * FG_CTAS);

    // ---- phase 3: prefix of partials + finalize offsets/cursors ----
    {
        int s = 0;
        for (int i = threadIdx.x; i < blockIdx.x; i += 256) s += g_part[i];
        sred[threadIdx.x] = s;
        __syncthreads();
        #pragma unroll
        for (int off = 128; off > 0; off >>= 1) {
            if (threadIdx.x < off) sred[threadIdx.x] += sred[threadIdx.x + off];
            __syncthreads();
        }
        int prefix = sred[0];
        for (int t = threadIdx.x; t < CHUNK_N; t += 256) {
            int idx = base + t;
            if (idx < N_NODES) {
                int o = soff[t] + prefix;
                g_offset[idx] = o;
                g_cursor[idx] = o;
            }
        }
    }
    grid_barrier(3 * FG_CTAS);

    // ---- phase 4: CSR fill ----
    for (int t = gtid; t < E_EDGES / 4; t += nthr) {
        int4 r = er4[t];
        int b4 = t * 4;
        int p0 = atomicAdd(&g_cursor[r.x], 1); g_edge_ids[p0] = b4 + 0;
        int p1 = atomicAdd(&g_cursor[r.y], 1); g_edge_ids[p1] = b4 + 1;
        int p2 = atomicAdd(&g_cursor[r.z], 1); g_edge_ids[p2] = b4 + 2;
        int p3 = atomicAdd(&g_cursor[r.w], 1); g_edge_ids[p3] = b4 + 3;
    }
    grid_barrier(4 * FG_CTAS);

    // ---- phase 5: gather segment-sum (warp per node, predicated 8-wide) ----
    const int lane   = threadIdx.x & 31;
    const int gw     = gtid >> 5;
    const int nwarps = nthr >> 5;
    const float4* ea4 = (const float4*)edge_attr;

    for (int node = gw; node < N_NODES; node += nwarps) {
        int start = g_offset[node];
        int cnt   = g_count[node];
        float4 acc = make_float4(0.f, 0.f, 0.f, 0.f);
        for (int i = 0; i < cnt; i += 8) {
            const int rem = cnt - i;
            int e[8];
            #pragma unroll
            for (int u = 0; u < 8; u++) {
                int idx = start + i + u;
                e[u] = g_edge_ids[min(idx, E_EDGES - 1)];
            }
            float4 v[8];
            #pragma unroll
            for (int u = 0; u < 8; u++) {
                if (u < rem) v[u] = __ldcs(&ea4[(size_t)e[u] * 32 + lane]);
                else         v[u] = make_float4(0.f, 0.f, 0.f, 0.f);
            }
            #pragma unroll
            for (int u = 0; u < 8; u++) {
                acc.x += v[u].x; acc.y += v[u].y; acc.z += v[u].z; acc.w += v[u].w;
            }
        }
        ((float4*)g_sum)[(size_t)node * 32 + lane] = acc;
    }
}

// ---------------- MLP via mma.sync (256 thr, TILE_M=128, nf-pair jam) --------
__device__ __forceinline__ void mma_bf16(float4& d,
    uint32_t a0, uint32_t a1, uint32_t a2, uint32_t a3,
    uint32_t b0, uint32_t b1) {
    asm volatile(
        "mma.sync.aligned.m16n8k16.row.col.f32.bf16.bf16.f32 "
        "{%0,%1,%2,%3}, {%4,%5,%6,%7}, {%8,%9}, {%0,%1,%2,%3};"
        : "+f"(d.x), "+f"(d.y), "+f"(d.z), "+f"(d.w)
        : "r"(a0), "r"(a1), "r"(a2), "r"(a3), "r"(b0), "r"(b1));
}
__device__ __forceinline__ void split2(float a, float b, uint32_t& hi, uint32_t& lo) {
    __nv_bfloat16 ha = __float2bfloat16_rn(a);
    __nv_bfloat16 hb = __float2bfloat16_rn(b);
    __nv_bfloat162 H; H.x = ha; H.y = hb;
    hi = *(uint32_t*)&H;
    __nv_bfloat162 L;
    L.x = __float2bfloat16_rn(a - __bfloat162float(ha));
    L.y = __float2bfloat16_rn(b - __bfloat162float(hb));
    lo = *(uint32_t*)&L;
}

#define TILE_M  128
#define N_TILES ((N_NODES + TILE_M - 1) / TILE_M)   // 391
#define W1_BYTES (128 * 68 * 16)   // 139264
#define W2_BYTES (128 * 36 * 16)   // 73728
#define MLP_SMEM (W1_BYTES + W2_BYTES + 256 * 4)    // 214016

__global__ __launch_bounds__(256, 1)
void mlp_mma_kernel(const float* __restrict__ x,
                    const float* __restrict__ W1, const float* __restrict__ b1,
                    const float* __restrict__ W2, const float* __restrict__ b2,
                    float* __restrict__ out) {
    extern __shared__ char smem[];
    char*  W1i = smem;
    char*  W2i = smem + W1_BYTES;
    float* b1s = (float*)(smem + W1_BYTES + W2_BYTES);
    float* b2s = b1s + 128;

    const int tid = threadIdx.x;

    for (int i = tid; i < 256 * 128; i += 256) {
        int k = i >> 7, j = i & 127;
        float v = W1[i];
        __nv_bfloat16 h = __float2bfloat16_rn(v);
        __nv_bfloat16 l = __float2bfloat16_rn(v - __bfloat162float(h));
        int ks = k >> 4, m = k & 15;
        int q = (m & 7) >> 1, s = m & 1, t = m >> 3;
        char* p8 = W1i + ((j * 68 + ks * 4 + q) << 4) + t * 4 + s * 2;
        *(__nv_bfloat16*)p8 = h;
        *(__nv_bfloat16*)(p8 + 8) = l;
    }
    for (int i = tid; i < 128 * 128; i += 256) {
        int k = i >> 7, j = i & 127;
        float v = W2[i];
        __nv_bfloat16 h = __float2bfloat16_rn(v);
        __nv_bfloat16 l = __float2bfloat16_rn(v - __bfloat162float(h));
        int ks = k >> 4, m = k & 15;
        int q = (m & 7) >> 1, s = m & 1, t = m >> 3;
        char* p8 = W2i + ((j * 36 + ks * 4 + q) << 4) + t * 4 + s * 2;
        *(__nv_bfloat16*)p8 = h;
        *(__nv_bfloat16*)(p8 + 8) = l;
    }
    if (tid < 128) { b1s[tid] = b1[tid]; b2s[tid] = b2[tid]; }
    __syncthreads();

    const int w    = tid >> 5;
    const int lane = tid & 31;
    const int p    = lane >> 2;
    const int q    = lane & 3;
    const char* B1p = W1i + ((p * 68 + q) << 4);
    const char* B2p = W2i + ((p * 36 + q) << 4);

    for (int tile = blockIdx.x; tile < N_TILES; tile += gridDim.x) {
        const int row0 = tile * TILE_M + w * 16 + p;
        const int row1 = row0 + 8;
        const bool ok0 = row0 < N_NODES;
        const bool ok1 = row1 < N_NODES;
        const float* xr0 = x + (size_t)row0 * 128;
        const float* xr1 = x + (size_t)row1 * 128;
        const float* sr0 = g_sum + (size_t)row0 * 128;
        const float* sr1 = g_sum + (size_t)row1 * 128;

        float4 acc[16];
        #pragma unroll
        for (int nf = 0; nf < 16; nf++) acc[nf] = make_float4(0.f, 0.f, 0.f, 0.f);

        #pragma unroll
        for (int ks = 0; ks < 16; ks++) {
            const float* p0 = (ks < 8) ? xr0 : sr0;
            const float* p1 = (ks < 8) ? xr1 : sr1;
            const int ko = (ks & 7) * 16 + q * 2;
            float2 z = make_float2(0.f, 0.f);
            float2 v00 = ok0 ? *(const float2*)(p0 + ko)     : z;
            float2 v01 = ok0 ? *(const float2*)(p0 + ko + 8) : z;
            float2 v10 = ok1 ? *(const float2*)(p1 + ko)     : z;
            float2 v11 = ok1 ? *(const float2*)(p1 + ko + 8) : z;
            uint32_t a0h, a0l, a1h, a1l, a2h, a2l, a3h, a3l;
            split2(v00.x, v00.y, a0h, a0l);
            split2(v10.x, v10.y, a1h, a1l);
            split2(v01.x, v01.y, a2h, a2l);
            split2(v11.x, v11.y, a3h, a3l);
            const char* wp = B1p + ks * 64;
            // nf-pair jam: alternate accumulators to widen dependency gaps
            #pragma unroll
            for (int nf = 0; nf < 16; nf += 2) {
                uint4 bw0 = *(const uint4*)(wp + nf * 8704);         // 8*68*16
                uint4 bw1 = *(const uint4*)(wp + (nf + 1) * 8704);
                mma_bf16(acc[nf],     a0h, a1h, a2h, a3h, bw0.x, bw0.y);
                mma_bf16(acc[nf + 1], a0h, a1h, a2h, a3h, bw1.x, bw1.y);
                mma_bf16(acc[nf],     a0h, a1h, a2h, a3h, bw0.z, bw0.w);
                mma_bf16(acc[nf + 1], a0h, a1h, a2h, a3h, bw1.z, bw1.w);
                mma_bf16(acc[nf],     a0l, a1l, a2l, a3l, bw0.x, bw0.y);
                mma_bf16(acc[nf + 1], a0l, a1l, a2l, a3l, bw1.x, bw1.y);
            }
        }

        uint32_t ah[8][4], al[8][4];
        #pragma unroll
        for (int ks2 = 0; ks2 < 8; ks2++) {
            #pragma unroll
            for (int half = 0; half < 2; half++) {
                const int nf = ks2 * 2 + half;
                float2 bv = *(const float2*)&b1s[nf * 8 + q * 2];
                float hx = fmaxf(acc[nf].x + bv.x, 0.f);
                float hy = fmaxf(acc[nf].y + bv.y, 0.f);
                float hz = fmaxf(acc[nf].z + bv.x, 0.f);
                float hw = fmaxf(acc[nf].w + bv.y, 0.f);
                split2(hx, hy, ah[ks2][half * 2 + 0], al[ks2][half * 2 + 0]);
                split2(hz, hw, ah[ks2][half * 2 + 1], al[ks2][half * 2 + 1]);
            }
        }

        float4 acc2[16];
        #pragma unroll
        for (int nf = 0; nf < 16; nf++) acc2[nf] = make_float4(0.f, 0.f, 0.f, 0.f);

        #pragma unroll
        for (int ks2 = 0; ks2 < 8; ks2++) {
            const char* wp = B2p + ks2 * 64;
            #pragma unroll
            for (int nf = 0; nf < 16; nf += 2) {
                uint4 bw0 = *(const uint4*)(wp + nf * 4608);         // 8*36*16
                uint4 bw1 = *(const uint4*)(wp + (nf + 1) * 4608);
                mma_bf16(acc2[nf],     ah[ks2][0], ah[ks2][1], ah[ks2][2], ah[ks2][3], bw0.x, bw0.y);
                mma_bf16(acc2[nf + 1], ah[ks2][0], ah[ks2][1], ah[ks2][2], ah[ks2][3], bw1.x, bw1.y);
                mma_bf16(acc2[nf],     ah[ks2][0], ah[ks2][1], ah[ks2][2], ah[ks2][3], bw0.z, bw0.w);
                mma_bf16(acc2[nf + 1], ah[ks2][0], ah[ks2][1], ah[ks2][2], ah[ks2][3], bw1.z, bw1.w);
                mma_bf16(acc2[nf],     al[ks2][0], al[ks2][1], al[ks2][2], al[ks2][3], bw0.x, bw0.y);
                mma_bf16(acc2[nf + 1], al[ks2][0], al[ks2][1], al[ks2][2], al[ks2][3], bw1.x, bw1.y);
            }
        }

        #pragma unroll
        for (int nf = 0; nf < 16; nf++) {
            const int j = nf * 8 + q * 2;
            float2 bv = *(const float2*)&b2s[j];
            if (ok0) {
                float2 xr = *(const float2*)(xr0 + j);
                float2 o = make_float2(acc2[nf].x + bv.x + xr.x,
                                       acc2[nf].y + bv.y + xr.y);
                *(float2*)(out + (size_t)row0 * 128 + j) = o;
            }
            if (ok1) {
                float2 xr = *(const float2*)(xr1 + j);
                float2 o = make_float2(acc2[nf].z + bv.x + xr.x,
                                       acc2[nf].w + bv.y + xr.y);
                *(float2*)(out + (size_t)row1 * 128 + j) = o;
            }
        }
    }
}

// ---------------- launcher ---------------------------------------------------
extern "C" void kernel_launch(void* const* d_in, const int* in_sizes, int n_in,
                              void* d_out, int out_size) {
    const float* x          = (const float*)d_in[0];
    const int*   edge_row   = (const int*)d_in[1];   // int64 downcast; first E = row
    const float* edge_attr  = (const float*)d_in[2];
    const float* W1         = (const float*)d_in[5];
    const float* b1         = (const float*)d_in[6];
    const float* W2         = (const float*)d_in[7];
    const float* b2         = (const float*)d_in[8];
    float*       out        = (float*)d_out;

    void* gcnt = nullptr;
    cudaGetSymbolAddress(&gcnt, g_count);
    cudaMemsetAsync(gcnt, 0, N_NODES * sizeof(int));
    void* gbar = nullptr;
    cudaGetSymbolAddress(&gbar, g_bar);
    cudaMemsetAsync(gbar, 0, sizeof(int));

    prologue_kernel<<<FG_CTAS, 256>>>((const int4*)edge_row, edge_attr);   // kernel 1
    cudaFuncSetAttribute(mlp_mma_kernel, cudaFuncAttributeMaxDynamicSharedMemorySize, MLP_SMEM);
    mlp_mma_kernel<<<148, 256, MLP_SMEM>>>(x, W1, b1, W2, b2, out);        // kernel 2
}